// round 7
// baseline (speedup 1.0000x reference)
#include <cuda_runtime.h>

#define BATCH 64
#define PIX   196
#define ENCD  2048
#define ATTD  512
#define DECD  512
#define EMBD  512
#define TT    32
#define NSTEP 31
#define VOC   30000
#define XH_W  3072   // per batch row: emb[512](unused) | context[2048] | h[512]
#define GATE_N 1536
#define MROWS (NSTEP * BATCH)   // 1984

// ---------------- device scratch ----------------
__device__ float g_att1[(size_t)BATCH * PIX * ATTD];     // 25.7 MB
__device__ float g_xh[BATCH * XH_W];
__device__ float g_gates[2 * BATCH * GATE_N];            // [0]=gi(ctx part), [1]=gh
__device__ float g_hall[(size_t)MROWS * DECD];
__device__ float g_alpha[BATCH * PIX];
__device__ float g_emball[(size_t)MROWS * EMBD];         // 4 MB
__device__ float g_giemb[(size_t)MROWS * GATE_N];        // 12.2 MB (includes b_ih)

// ---------------- utility ----------------
__global__ void zerok(float* p, int n) {
    int i = blockIdx.x * blockDim.x + threadIdx.x;
    if (i < n) p[i] = 0.f;
}

__device__ __forceinline__ unsigned int f2tf32(float f) {
    unsigned int r;
    asm("cvt.rna.tf32.f32 %0, %1;" : "=r"(r) : "f"(f));
    return r;
}

__device__ __forceinline__ float tanh_fast(float x) {
    float y;
    asm("tanh.approx.f32 %0, %1;" : "=f"(y) : "f"(x));
    return y;
}

__device__ __forceinline__ void mma_tf32(float* c,
    unsigned int a0, unsigned int a1, unsigned int a2, unsigned int a3,
    unsigned int b0, unsigned int b1)
{
    asm("mma.sync.aligned.m16n8k8.row.col.f32.tf32.tf32.f32 "
        "{%0,%1,%2,%3}, {%4,%5,%6,%7}, {%8,%9}, {%0,%1,%2,%3};"
        : "+f"(c[0]), "+f"(c[1]), "+f"(c[2]), "+f"(c[3])
        : "r"(a0), "r"(a1), "r"(a2), "r"(a3), "r"(b0), "r"(b1));
}

// ---------------- tf32 GEMM: C = A * B^T + bias,  tile 128x128 -------------
// Paired-k smem: uint2 element (k, k+4) at [row][k8*4 + ((tig)^sw(row))],
// sw(row) = ((row>>2)&3) ^ (row&3)  -> conflict-light LDS.64 frag loads.
// 256 threads = 8 warps: wm=(warp&3)*32, wn=(warp>>2)*64; warp tile 32x64.
// REMAP=1: row m = t*64+b -> C[((b*31+t)*VOC + n)]
template <int REMAP>
__global__ __launch_bounds__(256) void gemm_tf32(
    const float* __restrict__ A, int lda,
    const float* __restrict__ Bm, int ldb,
    const float* __restrict__ bias, float* __restrict__ C,
    int M, int N, int K)
{
    __shared__ uint2 sA2[128][20];   // 16 pairs + pad4
    __shared__ uint2 sB2[128][20];
    const int tid = threadIdx.x;
    const int warp = tid >> 5, lane = tid & 31;
    const int m0 = blockIdx.x * 128, n0 = blockIdx.y * 128;
    const int wm = (warp & 3) * 32;
    const int wn = (warp >> 2) * 64;
    const int gid = lane >> 2;   // 0..7
    const int tig = lane & 3;    // 0..3

    float acc[2][8][4];
#pragma unroll
    for (int mt = 0; mt < 2; mt++)
#pragma unroll
        for (int nt = 0; nt < 8; nt++)
#pragma unroll
            for (int r = 0; r < 4; r++) acc[mt][nt][r] = 0.f;

    for (int kc = 0; kc < K; kc += 32) {
        // fill A: 128x32 = 1024 float4
#pragma unroll
        for (int it = 0; it < 4; it++) {
            int v = tid + it * 256;
            int row = v >> 3, c4 = v & 7;
            int gm = m0 + row;
            float4 f = make_float4(0.f, 0.f, 0.f, 0.f);
            if (gm < M) f = *(const float4*)&A[(size_t)gm * lda + kc + c4 * 4];
            int sw = ((row >> 2) & 3) ^ (row & 3);
            unsigned* base = (unsigned*)&sA2[row][(c4 >> 1) * 4];
            int half = c4 & 1;
            base[((0 ^ sw) << 1) + half] = f2tf32(f.x);
            base[((1 ^ sw) << 1) + half] = f2tf32(f.y);
            base[((2 ^ sw) << 1) + half] = f2tf32(f.z);
            base[((3 ^ sw) << 1) + half] = f2tf32(f.w);
        }
        // fill B: 128x32 = 1024 float4
#pragma unroll
        for (int it = 0; it < 4; it++) {
            int v = tid + it * 256;
            int row = v >> 3, c4 = v & 7;
            int gn = n0 + row;
            float4 f = make_float4(0.f, 0.f, 0.f, 0.f);
            if (gn < N) f = *(const float4*)&Bm[(size_t)gn * ldb + kc + c4 * 4];
            int sw = ((row >> 2) & 3) ^ (row & 3);
            unsigned* base = (unsigned*)&sB2[row][(c4 >> 1) * 4];
            int half = c4 & 1;
            base[((0 ^ sw) << 1) + half] = f2tf32(f.x);
            base[((1 ^ sw) << 1) + half] = f2tf32(f.y);
            base[((2 ^ sw) << 1) + half] = f2tf32(f.z);
            base[((3 ^ sw) << 1) + half] = f2tf32(f.w);
        }
        __syncthreads();
#pragma unroll
        for (int k8 = 0; k8 < 4; k8++) {
            uint2 bfrag[8];
#pragma unroll
            for (int nt = 0; nt < 8; nt++) {
                int rB = wn + nt * 8 + gid;
                int swb = ((rB >> 2) & 3) ^ (rB & 3);
                bfrag[nt] = sB2[rB][k8 * 4 + (tig ^ swb)];
            }
#pragma unroll
            for (int mt = 0; mt < 2; mt++) {
                int rA = wm + mt * 16 + gid;
                int swa = ((rA >> 2) & 3) ^ (rA & 3);
                uint2 lo = sA2[rA][k8 * 4 + (tig ^ swa)];
                uint2 hi = sA2[rA + 8][k8 * 4 + (tig ^ (swa ^ 2))];
#pragma unroll
                for (int nt = 0; nt < 8; nt++)
                    mma_tf32(acc[mt][nt], lo.x, hi.x, lo.y, hi.y,
                             bfrag[nt].x, bfrag[nt].y);
            }
        }
        __syncthreads();
    }

    // epilogue: c0,c1 -> row gid, cols 2tig,2tig+1; c2,c3 -> row gid+8
#pragma unroll
    for (int mt = 0; mt < 2; mt++) {
#pragma unroll
        for (int half = 0; half < 2; half++) {
            int gm = m0 + wm + mt * 16 + gid + half * 8;
            if (gm >= M) continue;
            size_t base;
            if (REMAP) {
                int t = gm >> 6, bb = gm & 63;
                base = ((size_t)bb * NSTEP + t) * VOC;
            } else {
                base = (size_t)gm * N;
            }
#pragma unroll
            for (int nt = 0; nt < 8; nt++) {
                int gn = n0 + wn + nt * 8 + tig * 2;
                if (gn >= N) continue;
                float2 v;
                v.x = acc[mt][nt][half * 2 + 0] + bias[gn];
                v.y = acc[mt][nt][half * 2 + 1] + bias[gn + 1];
                *(float2*)&C[base + gn] = v;
            }
        }
    }
}

// ---------------- GRU gate GEMMs (per step) --------------------------------
// y==0: gi_ctx = ctx @ W_ih[:,512:2560]^T  (K=2048, 8-way split-K)
// y==1: gh     = h   @ W_hh^T              (K=512,  8-way split-K)
// 64x64 tile, 256 threads, thread computes 4x4. Transposed+swizzled smem.
__global__ __launch_bounds__(256) void gru_gemms(
    const float* __restrict__ xh_base,
    const float* __restrict__ W_ih, const float* __restrict__ W_hh)
{
    const int y = blockIdx.y;
    const int z = blockIdx.z;
    const float* A  = y ? xh_base + 2560 : xh_base + 512;
    const float* Bm = y ? W_hh : W_ih + 512;
    const int ldb = y ? 512 : 2560;
    const int Kz  = y ? 64 : 256;           // K/8
    const int k0  = z * Kz;
    float* C = g_gates + (y ? (size_t)BATCH * GATE_N : 0);

    __shared__ float sAt[64][68];   // [k][row], group-XOR swizzled
    __shared__ float sBt[64][68];
    const int tid = threadIdx.x;
    const int n0 = blockIdx.x * 64;
    const int tr = (tid >> 4) << 2;
    const int tc = (tid & 15) << 2;

    float acc[4][4];
#pragma unroll
    for (int i = 0; i < 4; i++)
#pragma unroll
        for (int j = 0; j < 4; j++) acc[i][j] = 0.f;

    for (int kc = 0; kc < Kz; kc += 64) {
#pragma unroll
        for (int it = 0; it < 4; it++) {
            int v = tid + it * 256;
            int row = v >> 4, c4 = v & 15;
            int g = row >> 2, r3 = row & 3;
            float4 fa = *(const float4*)&A[(size_t)row * XH_W + k0 + kc + c4 * 4];
            float4 fb = *(const float4*)&Bm[(size_t)(n0 + row) * ldb + k0 + kc + c4 * 4];
            float av[4] = {fa.x, fa.y, fa.z, fa.w};
            float bv[4] = {fb.x, fb.y, fb.z, fb.w};
#pragma unroll
            for (int j = 0; j < 4; j++) {
                int k = c4 * 4 + j;
                int pc = ((g ^ (k & 15)) << 2) + r3;
                sAt[k][pc] = av[j];
                sBt[k][pc] = bv[j];
            }
        }
        __syncthreads();
#pragma unroll 8
        for (int k = 0; k < 64; k++) {
            int xr = ((tr >> 2) ^ (k & 15)) << 2;
            int xc = ((tc >> 2) ^ (k & 15)) << 2;
            float2 a0 = *(const float2*)&sAt[k][xr];
            float2 a1 = *(const float2*)&sAt[k][xr + 2];
            float2 b0 = *(const float2*)&sBt[k][xc];
            float2 b1 = *(const float2*)&sBt[k][xc + 2];
            float av[4] = {a0.x, a0.y, a1.x, a1.y};
            float bv[4] = {b0.x, b0.y, b1.x, b1.y};
#pragma unroll
            for (int i = 0; i < 4; i++)
#pragma unroll
                for (int j = 0; j < 4; j++) acc[i][j] += av[i] * bv[j];
        }
        __syncthreads();
    }
#pragma unroll
    for (int i = 0; i < 4; i++)
#pragma unroll
        for (int j = 0; j < 4; j++)
            atomicAdd(&C[(size_t)(tr + i) * GATE_N + n0 + tc + j], acc[i][j]);
}

// ---------------- attention scores + softmax (block per batch) -------------
__global__ __launch_bounds__(256) void attn_scores(
    const float* __restrict__ W_dec, const float* __restrict__ b_dec,
    const float* __restrict__ w_full, const float* __restrict__ b_full)
{
    const int b = blockIdx.x;
    const int tid = threadIdx.x;
    const int lane = tid & 31, warp = tid >> 5;
    __shared__ __align__(16) float sh[DECD];
    __shared__ __align__(16) float satt2[ATTD];
    __shared__ __align__(16) float se[PIX];
    __shared__ float sred[16];
    float* xh = g_xh + (size_t)b * XH_W;

    // zero this batch's gate accumulators
    {
        float4* gi = (float4*)(g_gates + (size_t)b * GATE_N);
        float4* gh = (float4*)(g_gates + (size_t)BATCH * GATE_N + (size_t)b * GATE_N);
        float4 z4 = make_float4(0.f, 0.f, 0.f, 0.f);
#pragma unroll
        for (int i = tid; i < GATE_N / 4; i += 256) { gi[i] = z4; gh[i] = z4; }
    }

    for (int i = tid; i < DECD; i += 256) sh[i] = xh[2560 + i];
    __syncthreads();

    // att2 = h @ W_dec^T + b_dec
    const float4* shv = (const float4*)sh;
    for (int a = warp; a < ATTD; a += 8) {
        const float4* wr = (const float4*)(W_dec + (size_t)a * DECD);
        float s = 0.f;
#pragma unroll
        for (int k = lane; k < 128; k += 32) {
            float4 w = wr[k]; float4 h4 = shv[k];
            s += w.x * h4.x + w.y * h4.y + w.z * h4.z + w.w * h4.w;
        }
#pragma unroll
        for (int o = 16; o; o >>= 1) s += __shfl_xor_sync(0xffffffffu, s, o);
        if (lane == 0) satt2[a] = s + b_dec[a];
    }
    __syncthreads();

    // scores
    const float* att1b = g_att1 + (size_t)b * PIX * ATTD;
    const float4* satt2v = (const float4*)satt2;
    const float4* wfv = (const float4*)w_full;
    for (int p = warp; p < PIX; p += 8) {
        const float4* ar = (const float4*)(att1b + (size_t)p * ATTD);
        float s = 0.f;
#pragma unroll
        for (int a = lane; a < 128; a += 32) {
            float4 x = ar[a]; float4 t2 = satt2v[a]; float4 w = wfv[a];
            s += tanh_fast(x.x + t2.x) * w.x + tanh_fast(x.y + t2.y) * w.y
               + tanh_fast(x.z + t2.z) * w.z + tanh_fast(x.w + t2.w) * w.w;
        }
#pragma unroll
        for (int o = 16; o; o >>= 1) s += __shfl_xor_sync(0xffffffffu, s, o);
        if (lane == 0) se[p] = s + b_full[0];
    }
    __syncthreads();

    // softmax over 196
    float lm = -3.4e38f;
    for (int p = tid; p < PIX; p += 256) lm = fmaxf(lm, se[p]);
#pragma unroll
    for (int o = 16; o; o >>= 1) lm = fmaxf(lm, __shfl_xor_sync(0xffffffffu, lm, o));
    if (lane == 0) sred[warp] = lm;
    __syncthreads();
    if (warp == 0) {
        float v = (lane < 8) ? sred[lane] : -3.4e38f;
#pragma unroll
        for (int o = 16; o; o >>= 1) v = fmaxf(v, __shfl_xor_sync(0xffffffffu, v, o));
        if (lane == 0) sred[8] = v;
    }
    __syncthreads();
    const float gmax = sred[8];
    float ls = 0.f;
    for (int p = tid; p < PIX; p += 256) {
        float ex = expf(se[p] - gmax);
        se[p] = ex;
        ls += ex;
    }
#pragma unroll
    for (int o = 16; o; o >>= 1) ls += __shfl_xor_sync(0xffffffffu, ls, o);
    if (lane == 0) sred[warp] = ls;
    __syncthreads();
    if (warp == 0) {
        float v = (lane < 8) ? sred[lane] : 0.f;
#pragma unroll
        for (int o = 16; o; o >>= 1) v += __shfl_xor_sync(0xffffffffu, v, o);
        if (lane == 0) sred[9] = v;
    }
    __syncthreads();
    const float sinv = 1.f / sred[9];
    for (int p = tid; p < PIX; p += 256)
        g_alpha[b * PIX + p] = se[p] * sinv;
}

// ---------------- context gather: grid (64, 4), 128 threads ----------------
__global__ __launch_bounds__(128) void attn_context(const float* __restrict__ enc)
{
    const int b = blockIdx.x;
    const int tid = threadIdx.x;
    const int col4 = blockIdx.y * 128 + tid;     // float4 index 0..511
    __shared__ float sa[PIX];
    if (tid < PIX) sa[tid] = g_alpha[b * PIX + tid];
    if (tid + 128 < PIX) sa[tid + 128] = g_alpha[b * PIX + tid + 128];
    __syncthreads();

    const float4* encb = (const float4*)(enc + (size_t)b * PIX * ENCD);
    float4 c = make_float4(0.f, 0.f, 0.f, 0.f);
#pragma unroll 4
    for (int p = 0; p < PIX; p++) {
        const float ap = sa[p];
        float4 v = encb[(size_t)p * 512 + col4];
        c.x += ap * v.x; c.y += ap * v.y; c.z += ap * v.z; c.w += ap * v.w;
    }
    ((float4*)(g_xh + (size_t)b * XH_W + 512))[col4] = c;
}

// ---------------- GRU gate activations + h update --------------------------
__global__ __launch_bounds__(256) void gru_gates(
    int t, const float* __restrict__ b_hh)
{
    int idx = blockIdx.x * 256 + threadIdx.x;
    if (idx >= BATCH * DECD) return;
    int b = idx >> 9, d = idx & 511;
    const float* gi = g_gates + (size_t)b * GATE_N;
    const float* gh = g_gates + (size_t)BATCH * GATE_N + (size_t)b * GATE_N;
    const float* ge = g_giemb + ((size_t)t * BATCH + b) * GATE_N;  // incl b_ih
    float rr = (gi[d] + ge[d]) + (gh[d] + b_hh[d]);
    float zz = (gi[512 + d] + ge[512 + d]) + (gh[512 + d] + b_hh[512 + d]);
    float inp = gi[1024 + d] + ge[1024 + d];
    float hnp = gh[1024 + d] + b_hh[1024 + d];
    float r = 1.f / (1.f + expf(-rr));
    float z = 1.f / (1.f + expf(-zz));
    float n = tanhf(inp + r * hnp);
    float* xh = g_xh + (size_t)b * XH_W;
    float hold = xh[2560 + d];
    float hnew = (1.f - z) * n + z * hold;
    xh[2560 + d] = hnew;
    g_hall[((size_t)t * BATCH + b) * DECD + d] = hnew;
}

// ---------------- embedding gather for all steps ---------------------------
__global__ __launch_bounds__(128) void gather_embs(
    const int* __restrict__ captions, const float* __restrict__ emb_table)
{
    int r = blockIdx.x;          // t*64+b
    int t = r >> 6, b = r & 63;
    int tok = captions[b * TT + t];
    const float4* src = (const float4*)(emb_table + (size_t)tok * EMBD);
    ((float4*)(g_emball + (size_t)r * EMBD))[threadIdx.x] = src[threadIdx.x];
}

__global__ void write_caplens(const int* __restrict__ caplens, float* __restrict__ out, int n)
{
    int i = threadIdx.x;
    if (i < n && i < BATCH) out[i] = (float)(caplens[i] - 1);
}

// ---------------- host ----------------
extern "C" void kernel_launch(void* const* d_in, const int* in_sizes, int n_in,
                              void* d_out, int out_size)
{
    const float* enc       = (const float*)d_in[0];
    const int*   captions  = (const int*)  d_in[1];
    const int*   caplens   = (const int*)  d_in[2];
    const float* emb_table = (const float*)d_in[3];
    const float* W_enc     = (const float*)d_in[4];
    const float* b_enc     = (const float*)d_in[5];
    const float* W_dec     = (const float*)d_in[6];
    const float* b_dec     = (const float*)d_in[7];
    const float* w_full    = (const float*)d_in[8];
    const float* b_full    = (const float*)d_in[9];
    const float* W_ih      = (const float*)d_in[10];
    const float* b_ih      = (const float*)d_in[11];
    const float* W_hh      = (const float*)d_in[12];
    const float* b_hh      = (const float*)d_in[13];
    const float* W_fc      = (const float*)d_in[14];
    const float* b_fc      = (const float*)d_in[15];
    float* out = (float*)d_out;

    float *att1p, *xhp, *hallp, *emballp, *giembp;
    cudaGetSymbolAddress((void**)&att1p, g_att1);
    cudaGetSymbolAddress((void**)&xhp, g_xh);
    cudaGetSymbolAddress((void**)&hallp, g_hall);
    cudaGetSymbolAddress((void**)&emballp, g_emball);
    cudaGetSymbolAddress((void**)&giembp, g_giemb);

    // h0 = 0
    zerok<<<(BATCH * XH_W + 255) / 256, 256>>>(xhp, BATCH * XH_W);

    // embeddings for all steps
    gather_embs<<<MROWS, 128>>>(captions, emb_table);

    // att1 = enc @ W_enc^T + b_enc : [12544,2048]x[2048,512]
    gemm_tf32<0><<<dim3(98, 4), 256>>>(enc, ENCD, W_enc, ENCD, b_enc, att1p,
                                       BATCH * PIX, ATTD, ENCD);

    // gi_emb = embs @ W_ih[:, :512]^T + b_ih : [1984,512]x[512,1536]
    gemm_tf32<0><<<dim3(16, 12), 256>>>(emballp, EMBD, W_ih, EMBD + ENCD,
                                        b_ih, giembp, MROWS, GATE_N, EMBD);

    for (int t = 0; t < NSTEP; t++) {
        attn_scores<<<BATCH, 256>>>(W_dec, b_dec, w_full, b_full);
        attn_context<<<dim3(BATCH, 4), 128>>>(enc);
        gru_gemms<<<dim3(24, 2, 8), 256>>>(xhp, W_ih, W_hh);
        gru_gates<<<(BATCH * DECD + 255) / 256, 256>>>(t, b_hh);
    }

    // logits = h_all @ W_fc^T + b_fc, stored as [b, t, v]
    gemm_tf32<1><<<dim3(16, 235), 256>>>(hallp, DECD, W_fc, DECD, b_fc, out,
                                         MROWS, VOC, DECD);

    long long NLOG = (long long)BATCH * NSTEP * VOC;
    if ((long long)out_size > NLOG) {
        int rem = (int)((long long)out_size - NLOG);
        write_caplens<<<1, 64>>>(caplens, out + NLOG, rem);
    }
}

// round 8
// speedup vs baseline: 1.0777x; 1.0777x over previous
#include <cuda_runtime.h>

#define BATCH 64
#define PIX   196
#define ENCD  2048
#define ATTD  512
#define DECD  512
#define EMBD  512
#define TT    32
#define NSTEP 31
#define VOC   30000
#define XH_W  3072   // per batch row: emb[512](unused) | context[2048] | h[512]
#define GATE_N 1536
#define MROWS (NSTEP * BATCH)   // 1984

// ---------------- device scratch ----------------
__device__ float g_att1[(size_t)BATCH * PIX * ATTD];     // 25.7 MB
__device__ float g_xh[BATCH * XH_W];
__device__ float g_gates[2 * BATCH * GATE_N];            // [0]=gi(ctx part), [1]=gh
__device__ float g_hall[(size_t)MROWS * DECD];
__device__ float g_emball[(size_t)MROWS * EMBD];         // 4 MB
__device__ float g_giemb[(size_t)MROWS * GATE_N];        // 12.2 MB (includes b_ih)

// ---------------- utility ----------------
__global__ void zerok(float* p, int n) {
    int i = blockIdx.x * blockDim.x + threadIdx.x;
    if (i < n) p[i] = 0.f;
}

__device__ __forceinline__ unsigned int f2tf32(float f) {
    unsigned int r;
    asm("cvt.rna.tf32.f32 %0, %1;" : "=r"(r) : "f"(f));
    return r;
}

__device__ __forceinline__ float tanh_fast(float x) {
    float y;
    asm("tanh.approx.f32 %0, %1;" : "=f"(y) : "f"(x));
    return y;
}

__device__ __forceinline__ void mma_tf32(float* c,
    unsigned int a0, unsigned int a1, unsigned int a2, unsigned int a3,
    unsigned int b0, unsigned int b1)
{
    asm("mma.sync.aligned.m16n8k8.row.col.f32.tf32.tf32.f32 "
        "{%0,%1,%2,%3}, {%4,%5,%6,%7}, {%8,%9}, {%0,%1,%2,%3};"
        : "+f"(c[0]), "+f"(c[1]), "+f"(c[2]), "+f"(c[3])
        : "r"(a0), "r"(a1), "r"(a2), "r"(a3), "r"(b0), "r"(b1));
}

// ---------------- tf32 GEMM: C = A * B^T + bias, tile 128x64, pipelined ----
// R4-proven fragment layout (sA[row][36], sB[row][36]); adds register
// prefetch of the next k-tile so LDG latency overlaps the mma loop.
// 256 threads = 8 warps (4m x 2n), warp tile 32x32.
// REMAP=1: row m = t*64+b -> C[((b*31+t)*VOC + n)]
template <int REMAP>
__global__ __launch_bounds__(256) void gemm_tf32(
    const float* __restrict__ A, int lda,
    const float* __restrict__ Bm, int ldb,
    const float* __restrict__ bias, float* __restrict__ C,
    int M, int N, int K)
{
    __shared__ unsigned int sA[128][36];
    __shared__ unsigned int sB[64][36];
    const int tid = threadIdx.x;
    const int warp = tid >> 5, lane = tid & 31;
    const int m0 = blockIdx.x * 128, n0 = blockIdx.y * 64;
    const int wm = (warp >> 1) * 32;       // 0,32,64,96
    const int wn = (warp & 1) * 32;        // 0,32
    const int gid = lane >> 2;             // 0..7
    const int tig = lane & 3;              // 0..3

    float acc[2][4][4];
#pragma unroll
    for (int mt = 0; mt < 2; mt++)
#pragma unroll
        for (int nt = 0; nt < 4; nt++)
#pragma unroll
            for (int r = 0; r < 4; r++) acc[mt][nt][r] = 0.f;

    const float4 z4 = make_float4(0.f, 0.f, 0.f, 0.f);
    float4 fA[4], fB[2];

    // prefetch tile kc=0
#pragma unroll
    for (int it = 0; it < 4; it++) {
        int v = tid + it * 256, row = v >> 3, c4 = v & 7, gm = m0 + row;
        fA[it] = (gm < M) ? *(const float4*)&A[(size_t)gm * lda + c4 * 4] : z4;
    }
#pragma unroll
    for (int it = 0; it < 2; it++) {
        int v = tid + it * 256, row = v >> 3, c4 = v & 7, gn = n0 + row;
        fB[it] = (gn < N) ? *(const float4*)&Bm[(size_t)gn * ldb + c4 * 4] : z4;
    }

    for (int kc = 0; kc < K; kc += 32) {
        // store current regs to smem (with tf32 convert)
#pragma unroll
        for (int it = 0; it < 4; it++) {
            int v = tid + it * 256, row = v >> 3, c4 = v & 7;
            unsigned int* d = &sA[row][c4 * 4];
            d[0] = f2tf32(fA[it].x); d[1] = f2tf32(fA[it].y);
            d[2] = f2tf32(fA[it].z); d[3] = f2tf32(fA[it].w);
        }
#pragma unroll
        for (int it = 0; it < 2; it++) {
            int v = tid + it * 256, row = v >> 3, c4 = v & 7;
            unsigned int* d = &sB[row][c4 * 4];
            d[0] = f2tf32(fB[it].x); d[1] = f2tf32(fB[it].y);
            d[2] = f2tf32(fB[it].z); d[3] = f2tf32(fB[it].w);
        }
        __syncthreads();

        // prefetch next tile while mma runs
        if (kc + 32 < K) {
            const int kn = kc + 32;
#pragma unroll
            for (int it = 0; it < 4; it++) {
                int v = tid + it * 256, row = v >> 3, c4 = v & 7, gm = m0 + row;
                fA[it] = (gm < M) ? *(const float4*)&A[(size_t)gm * lda + kn + c4 * 4] : z4;
            }
#pragma unroll
            for (int it = 0; it < 2; it++) {
                int v = tid + it * 256, row = v >> 3, c4 = v & 7, gn = n0 + row;
                fB[it] = (gn < N) ? *(const float4*)&Bm[(size_t)gn * ldb + kn + c4 * 4] : z4;
            }
        }

#pragma unroll
        for (int k8 = 0; k8 < 4; k8++) {
            const int kb = k8 * 8;
            unsigned int b0[4], b1[4];
#pragma unroll
            for (int nt = 0; nt < 4; nt++) {
                int rB = wn + nt * 8 + gid;
                b0[nt] = sB[rB][kb + tig];
                b1[nt] = sB[rB][kb + tig + 4];
            }
#pragma unroll
            for (int mt = 0; mt < 2; mt++) {
                int rA = wm + mt * 16 + gid;
                unsigned int a0 = sA[rA][kb + tig];
                unsigned int a1 = sA[rA + 8][kb + tig];
                unsigned int a2 = sA[rA][kb + tig + 4];
                unsigned int a3 = sA[rA + 8][kb + tig + 4];
#pragma unroll
                for (int nt = 0; nt < 4; nt++)
                    mma_tf32(acc[mt][nt], a0, a1, a2, a3, b0[nt], b1[nt]);
            }
        }
        __syncthreads();
    }

    // epilogue
#pragma unroll
    for (int mt = 0; mt < 2; mt++) {
#pragma unroll
        for (int half = 0; half < 2; half++) {
            int gm = m0 + wm + mt * 16 + gid + half * 8;
            if (gm >= M) continue;
            size_t base;
            if (REMAP) {
                int t = gm >> 6, bb = gm & 63;
                base = ((size_t)bb * NSTEP + t) * VOC;
            } else {
                base = (size_t)gm * N;
            }
#pragma unroll
            for (int nt = 0; nt < 4; nt++) {
                int gn = n0 + wn + nt * 8 + tig * 2;
                if (gn < N)     C[base + gn]     = acc[mt][nt][half * 2 + 0] + bias[gn];
                if (gn + 1 < N) C[base + gn + 1] = acc[mt][nt][half * 2 + 1] + bias[gn + 1];
            }
        }
    }
}

// ---------------- GRU gate GEMMs, tensor-core 3xTF32, one launch/step ------
// blockIdx.y 0..7 : gi_ctx = ctx @ W_ih[:,512:2560]^T  (K=2048, 8-way split)
// blockIdx.y 8..11: gh     = h   @ W_hh^T              (K=512,  4-way split)
// Tile 64(M=batch) x 128(N). 256 threads = 8 warps (2m x 4n).
// 3xTF32: acc += Ahi*Bhi + Ahi*Blo + Alo*Bhi  -> ~fp32 precision.
// Output: atomicAdd into g_gates (zeroed by attention_step).
__global__ __launch_bounds__(256) void gru_gemms_tc(
    const float* __restrict__ xh_base,
    const float* __restrict__ W_ih, const float* __restrict__ W_hh)
{
    const int yb = blockIdx.y;
    const bool is_gh = (yb >= 8);
    const int split = is_gh ? yb - 8 : yb;
    const int Kz = is_gh ? 128 : 256;
    const int k0 = split * Kz;
    const float* A  = is_gh ? xh_base + 2560 : xh_base + 512;
    const float* Bm = is_gh ? W_hh : W_ih + 512;
    const int ldb = is_gh ? 512 : 2560;
    float* C = g_gates + (is_gh ? (size_t)BATCH * GATE_N : 0);
    const int n0 = blockIdx.x * 128;

    __shared__ unsigned int sAhi[64][36], sAlo[64][36];
    __shared__ unsigned int sBhi[128][36], sBlo[128][36];
    const int tid = threadIdx.x;
    const int warp = tid >> 5, lane = tid & 31;
    const int wm = (warp & 1) * 32;        // 0,32
    const int wn = (warp >> 1) * 32;       // 0,32,64,96
    const int gid = lane >> 2;
    const int tig = lane & 3;

    float acc[2][4][4];
#pragma unroll
    for (int mt = 0; mt < 2; mt++)
#pragma unroll
        for (int nt = 0; nt < 4; nt++)
#pragma unroll
            for (int r = 0; r < 4; r++) acc[mt][nt][r] = 0.f;

    for (int kc = 0; kc < Kz; kc += 32) {
        // A fill: 64x32 = 512 float4, 2/thread
#pragma unroll
        for (int it = 0; it < 2; it++) {
            int v = tid + it * 256, row = v >> 3, c4 = v & 7;
            float4 f = *(const float4*)&A[(size_t)row * XH_W + k0 + kc + c4 * 4];
            float fv[4] = {f.x, f.y, f.z, f.w};
            unsigned int* dh = &sAhi[row][c4 * 4];
            unsigned int* dl = &sAlo[row][c4 * 4];
#pragma unroll
            for (int j = 0; j < 4; j++) {
                unsigned int hi = f2tf32(fv[j]);
                dh[j] = hi;
                dl[j] = f2tf32(fv[j] - __uint_as_float(hi));
            }
        }
        // B fill: 128x32 = 1024 float4, 4/thread
#pragma unroll
        for (int it = 0; it < 4; it++) {
            int v = tid + it * 256, row = v >> 3, c4 = v & 7;
            float4 f = *(const float4*)&Bm[(size_t)(n0 + row) * ldb + k0 + kc + c4 * 4];
            float fv[4] = {f.x, f.y, f.z, f.w};
            unsigned int* dh = &sBhi[row][c4 * 4];
            unsigned int* dl = &sBlo[row][c4 * 4];
#pragma unroll
            for (int j = 0; j < 4; j++) {
                unsigned int hi = f2tf32(fv[j]);
                dh[j] = hi;
                dl[j] = f2tf32(fv[j] - __uint_as_float(hi));
            }
        }
        __syncthreads();

#pragma unroll
        for (int k8 = 0; k8 < 4; k8++) {
            const int kb = k8 * 8;
            unsigned int bh0[4], bh1[4], bl0[4], bl1[4];
#pragma unroll
            for (int nt = 0; nt < 4; nt++) {
                int rB = wn + nt * 8 + gid;
                bh0[nt] = sBhi[rB][kb + tig];
                bh1[nt] = sBhi[rB][kb + tig + 4];
                bl0[nt] = sBlo[rB][kb + tig];
                bl1[nt] = sBlo[rB][kb + tig + 4];
            }
#pragma unroll
            for (int mt = 0; mt < 2; mt++) {
                int rA = wm + mt * 16 + gid;
                unsigned int ah0 = sAhi[rA][kb + tig];
                unsigned int ah1 = sAhi[rA + 8][kb + tig];
                unsigned int ah2 = sAhi[rA][kb + tig + 4];
                unsigned int ah3 = sAhi[rA + 8][kb + tig + 4];
                unsigned int al0 = sAlo[rA][kb + tig];
                unsigned int al1 = sAlo[rA + 8][kb + tig];
                unsigned int al2 = sAlo[rA][kb + tig + 4];
                unsigned int al3 = sAlo[rA + 8][kb + tig + 4];
#pragma unroll
                for (int nt = 0; nt < 4; nt++) {
                    mma_tf32(acc[mt][nt], ah0, ah1, ah2, ah3, bl0[nt], bl1[nt]);
                    mma_tf32(acc[mt][nt], al0, al1, al2, al3, bh0[nt], bh1[nt]);
                    mma_tf32(acc[mt][nt], ah0, ah1, ah2, ah3, bh0[nt], bh1[nt]);
                }
            }
        }
        __syncthreads();
    }

#pragma unroll
    for (int mt = 0; mt < 2; mt++)
#pragma unroll
        for (int half = 0; half < 2; half++) {
            int gm = wm + mt * 16 + gid + half * 8;      // 0..63
#pragma unroll
            for (int nt = 0; nt < 4; nt++) {
                int gn = n0 + wn + nt * 8 + tig * 2;
                atomicAdd(&C[(size_t)gm * GATE_N + gn],     acc[mt][nt][half * 2 + 0]);
                atomicAdd(&C[(size_t)gm * GATE_N + gn + 1], acc[mt][nt][half * 2 + 1]);
            }
        }
}

// ---------------- fused attention step (one block per batch element) -------
__global__ __launch_bounds__(256) void attention_step(
    const float* __restrict__ enc,
    const float* __restrict__ W_dec, const float* __restrict__ b_dec,
    const float* __restrict__ w_full, const float* __restrict__ b_full)
{
    const int b = blockIdx.x;
    const int tid = threadIdx.x;
    const int lane = tid & 31, warp = tid >> 5;
    __shared__ __align__(16) float sh[DECD];
    __shared__ __align__(16) float satt2[ATTD];
    __shared__ __align__(16) float se[PIX + 4];
    __shared__ float sred[16];
    float* xh = g_xh + (size_t)b * XH_W;

    // zero this batch's gate accumulators (consumed via atomicAdd by gru_gemms_tc)
    {
        float4* gi = (float4*)(g_gates + (size_t)b * GATE_N);
        float4* gh = (float4*)(g_gates + (size_t)BATCH * GATE_N + (size_t)b * GATE_N);
        float4 z4 = make_float4(0.f, 0.f, 0.f, 0.f);
#pragma unroll
        for (int i = tid; i < GATE_N / 4; i += 256) { gi[i] = z4; gh[i] = z4; }
    }

    for (int i = tid; i < DECD; i += 256) sh[i] = xh[2560 + i];
    if (tid >= PIX && tid < PIX + 4) se[tid] = 0.f;   // pad for unrolled context
    __syncthreads();

    // att2 = h @ W_dec^T + b_dec
    const float4* shv = (const float4*)sh;
    for (int a = warp; a < ATTD; a += 8) {
        const float4* wr = (const float4*)(W_dec + (size_t)a * DECD);
        float s = 0.f;
#pragma unroll
        for (int k = lane; k < 128; k += 32) {
            float4 w = wr[k]; float4 h4 = shv[k];
            s += w.x * h4.x + w.y * h4.y + w.z * h4.z + w.w * h4.w;
        }
#pragma unroll
        for (int o = 16; o; o >>= 1) s += __shfl_xor_sync(0xffffffffu, s, o);
        if (lane == 0) satt2[a] = s + b_dec[a];
    }
    __syncthreads();

    // scores e[p] = w_full . tanh(att1 + att2) + b_full
    const float* att1b = g_att1 + (size_t)b * PIX * ATTD;
    const float4* satt2v = (const float4*)satt2;
    const float4* wfv = (const float4*)w_full;
    for (int p = warp; p < PIX; p += 8) {
        const float4* ar = (const float4*)(att1b + (size_t)p * ATTD);
        float s = 0.f;
#pragma unroll
        for (int a = lane; a < 128; a += 32) {
            float4 x = ar[a]; float4 t2 = satt2v[a]; float4 w = wfv[a];
            s += tanh_fast(x.x + t2.x) * w.x + tanh_fast(x.y + t2.y) * w.y
               + tanh_fast(x.z + t2.z) * w.z + tanh_fast(x.w + t2.w) * w.w;
        }
#pragma unroll
        for (int o = 16; o; o >>= 1) s += __shfl_xor_sync(0xffffffffu, s, o);
        if (lane == 0) se[p] = s + b_full[0];
    }
    __syncthreads();

    // softmax over 196
    float lm = -3.4e38f;
    for (int p = tid; p < PIX; p += 256) lm = fmaxf(lm, se[p]);
#pragma unroll
    for (int o = 16; o; o >>= 1) lm = fmaxf(lm, __shfl_xor_sync(0xffffffffu, lm, o));
    if (lane == 0) sred[warp] = lm;
    __syncthreads();
    if (warp == 0) {
        float v = (lane < 8) ? sred[lane] : -3.4e38f;
#pragma unroll
        for (int o = 16; o; o >>= 1) v = fmaxf(v, __shfl_xor_sync(0xffffffffu, v, o));
        if (lane == 0) sred[8] = v;
    }
    __syncthreads();
    const float gmax = sred[8];
    float ls = 0.f;
    for (int p = tid; p < PIX; p += 256) {
        float ex = expf(se[p] - gmax);
        se[p] = ex;
        ls += ex;
    }
#pragma unroll
    for (int o = 16; o; o >>= 1) ls += __shfl_xor_sync(0xffffffffu, ls, o);
    if (lane == 0) sred[warp] = ls;
    __syncthreads();
    if (warp == 0) {
        float v = (lane < 8) ? sred[lane] : 0.f;
#pragma unroll
        for (int o = 16; o; o >>= 1) v += __shfl_xor_sync(0xffffffffu, v, o);
        if (lane == 0) sred[9] = v;
    }
    __syncthreads();
    const float sinv = 1.f / sred[9];
    for (int p = tid; p < PIX; p += 256) se[p] *= sinv;
    __syncthreads();

    // context = alpha . enc  (2 float4/thread, p unrolled x4 for MLP)
    const float4* encb = (const float4*)(enc + (size_t)b * PIX * ENCD);
    float4 c0 = make_float4(0.f, 0.f, 0.f, 0.f);
    float4 c1 = make_float4(0.f, 0.f, 0.f, 0.f);
#pragma unroll 1
    for (int p = 0; p < PIX; p += 4) {
        float a0 = se[p], a1 = se[p + 1], a2 = se[p + 2], a3 = se[p + 3];
        const float4* r0 = encb + (size_t)p * 512;
        float4 v00 = r0[tid],        v01 = r0[tid + 256];
        float4 v10 = r0[512 + tid],  v11 = r0[512 + tid + 256];
        float4 v20 = r0[1024 + tid], v21 = r0[1024 + tid + 256];
        float4 v30 = r0[1536 + tid], v31 = r0[1536 + tid + 256];
        c0.x += a0 * v00.x + a1 * v10.x + a2 * v20.x + a3 * v30.x;
        c0.y += a0 * v00.y + a1 * v10.y + a2 * v20.y + a3 * v30.y;
        c0.z += a0 * v00.z + a1 * v10.z + a2 * v20.z + a3 * v30.z;
        c0.w += a0 * v00.w + a1 * v10.w + a2 * v20.w + a3 * v30.w;
        c1.x += a0 * v01.x + a1 * v11.x + a2 * v21.x + a3 * v31.x;
        c1.y += a0 * v01.y + a1 * v11.y + a2 * v21.y + a3 * v31.y;
        c1.z += a0 * v01.z + a1 * v11.z + a2 * v21.z + a3 * v31.z;
        c1.w += a0 * v01.w + a1 * v11.w + a2 * v21.w + a3 * v31.w;
    }
    float4* ctx = (float4*)(xh + 512);
    ctx[tid] = c0;
    ctx[tid + 256] = c1;
}

// ---------------- GRU gate activations + h update --------------------------
__global__ __launch_bounds__(256) void gru_gates(
    int t, const float* __restrict__ b_hh)
{
    int idx = blockIdx.x * 256 + threadIdx.x;
    if (idx >= BATCH * DECD) return;
    int b = idx >> 9, d = idx & 511;
    const float* gi = g_gates + (size_t)b * GATE_N;
    const float* gh = g_gates + (size_t)BATCH * GATE_N + (size_t)b * GATE_N;
    const float* ge = g_giemb + ((size_t)t * BATCH + b) * GATE_N;  // incl b_ih
    float rr = (gi[d] + ge[d]) + (gh[d] + b_hh[d]);
    float zz = (gi[512 + d] + ge[512 + d]) + (gh[512 + d] + b_hh[512 + d]);
    float inp = gi[1024 + d] + ge[1024 + d];
    float hnp = gh[1024 + d] + b_hh[1024 + d];
    float r = 1.f / (1.f + expf(-rr));
    float z = 1.f / (1.f + expf(-zz));
    float n = tanhf(inp + r * hnp);
    float* xh = g_xh + (size_t)b * XH_W;
    float hold = xh[2560 + d];
    float hnew = (1.f - z) * n + z * hold;
    xh[2560 + d] = hnew;
    g_hall[((size_t)t * BATCH + b) * DECD + d] = hnew;
}

// ---------------- embedding gather for all steps ---------------------------
__global__ __launch_bounds__(128) void gather_embs(
    const int* __restrict__ captions, const float* __restrict__ emb_table)
{
    int r = blockIdx.x;          // t*64+b
    int t = r >> 6, b = r & 63;
    int tok = captions[b * TT + t];
    const float4* src = (const float4*)(emb_table + (size_t)tok * EMBD);
    ((float4*)(g_emball + (size_t)r * EMBD))[threadIdx.x] = src[threadIdx.x];
}

__global__ void write_caplens(const int* __restrict__ caplens, float* __restrict__ out, int n)
{
    int i = threadIdx.x;
    if (i < n && i < BATCH) out[i] = (float)(caplens[i] - 1);
}

// ---------------- host ----------------
extern "C" void kernel_launch(void* const* d_in, const int* in_sizes, int n_in,
                              void* d_out, int out_size)
{
    const float* enc       = (const float*)d_in[0];
    const int*   captions  = (const int*)  d_in[1];
    const int*   caplens   = (const int*)  d_in[2];
    const float* emb_table = (const float*)d_in[3];
    const float* W_enc     = (const float*)d_in[4];
    const float* b_enc     = (const float*)d_in[5];
    const float* W_dec     = (const float*)d_in[6];
    const float* b_dec     = (const float*)d_in[7];
    const float* w_full    = (const float*)d_in[8];
    const float* b_full    = (const float*)d_in[9];
    const float* W_ih      = (const float*)d_in[10];
    const float* b_ih      = (const float*)d_in[11];
    const float* W_hh      = (const float*)d_in[12];
    const float* b_hh      = (const float*)d_in[13];
    const float* W_fc      = (const float*)d_in[14];
    const float* b_fc      = (const float*)d_in[15];
    float* out = (float*)d_out;

    float *att1p, *xhp, *hallp, *emballp, *giembp;
    cudaGetSymbolAddress((void**)&att1p, g_att1);
    cudaGetSymbolAddress((void**)&xhp, g_xh);
    cudaGetSymbolAddress((void**)&hallp, g_hall);
    cudaGetSymbolAddress((void**)&emballp, g_emball);
    cudaGetSymbolAddress((void**)&giembp, g_giemb);

    // h0 = 0
    zerok<<<(BATCH * XH_W + 255) / 256, 256>>>(xhp, BATCH * XH_W);

    // embeddings for all steps
    gather_embs<<<MROWS, 128>>>(captions, emb_table);

    // att1 = enc @ W_enc^T + b_enc : [12544,2048]x[2048,512]
    gemm_tf32<0><<<dim3(98, 8), 256>>>(enc, ENCD, W_enc, ENCD, b_enc, att1p,
                                       BATCH * PIX, ATTD, ENCD);

    // gi_emb = embs @ W_ih[:, :512]^T + b_ih : [1984,512]x[512,1536]
    gemm_tf32<0><<<dim3(16, 24), 256>>>(emballp, EMBD, W_ih, EMBD + ENCD,
                                        b_ih, giembp, MROWS, GATE_N, EMBD);

    for (int t = 0; t < NSTEP; t++) {
        attention_step<<<BATCH, 256>>>(enc, W_dec, b_dec, w_full, b_full);
        gru_gemms_tc<<<dim3(12, 12), 256>>>(xhp, W_ih, W_hh);
        gru_gates<<<(BATCH * DECD + 255) / 256, 256>>>(t, b_hh);
    }

    // logits = h_all @ W_fc^T + b_fc, stored as [b, t, v]
    gemm_tf32<1><<<dim3(16, 469), 256>>>(hallp, DECD, W_fc, DECD, b_fc, out,
                                         MROWS, VOC, DECD);

    long long NLOG = (long long)BATCH * NSTEP * VOC;
    if ((long long)out_size > NLOG) {
        int rem = (int)((long long)out_size - NLOG);
        write_caplens<<<1, 64>>>(caplens, out + NLOG, rem);
    }
}

// round 10
// speedup vs baseline: 2.0461x; 1.8986x over previous
#include <cuda_runtime.h>

#define BATCH 64
#define PIX   196
#define ENCD  2048
#define ATTD  512
#define DECD  512
#define EMBD  512
#define TT    32
#define NSTEP 31
#define VOC   30000
#define XH_W  3072   // per batch row: emb[512](unused) | context[2048] | h[512]
#define GATE_N 1536
#define MROWS (NSTEP * BATCH)   // 1984

// ---------------- device scratch ----------------
__device__ float g_att1[(size_t)BATCH * PIX * ATTD];     // 25.7 MB
__device__ float g_xh[BATCH * XH_W];
__device__ float g_gates[2 * BATCH * GATE_N];            // [0]=gi(ctx part), [1]=gh
__device__ float g_hall[(size_t)MROWS * DECD];
__device__ float g_emball[(size_t)MROWS * EMBD];         // 4 MB
__device__ float g_giemb[(size_t)MROWS * GATE_N];        // 12.2 MB (includes b_ih)
__device__ float g_att2[BATCH * ATTD];
__device__ float g_alpha[BATCH * PIX];
// pre-split tf32 hi/lo weights (values stored as rounded floats)
__device__ float g_wih_hi[(size_t)GATE_N * ENCD];        // 12.6 MB  (W_ih ctx part)
__device__ float g_wih_lo[(size_t)GATE_N * ENCD];
__device__ float g_whh_hi[(size_t)2048 * DECD];          // rows: [W_hh(1536); W_dec(512)]
__device__ float g_whh_lo[(size_t)2048 * DECD];

// ---------------- utility ----------------
__global__ void zerok(float* p, int n) {
    int i = blockIdx.x * blockDim.x + threadIdx.x;
    if (i < n) p[i] = 0.f;
}

__device__ __forceinline__ unsigned int f2tf32(float f) {
    unsigned int r;
    asm("cvt.rna.tf32.f32 %0, %1;" : "=r"(r) : "f"(f));
    return r;
}

__device__ __forceinline__ float tanh_fast(float x) {
    float y;
    asm("tanh.approx.f32 %0, %1;" : "=f"(y) : "f"(x));
    return y;
}

__device__ __forceinline__ void mma_tf32(float* c,
    unsigned int a0, unsigned int a1, unsigned int a2, unsigned int a3,
    unsigned int b0, unsigned int b1)
{
    asm("mma.sync.aligned.m16n8k8.row.col.f32.tf32.tf32.f32 "
        "{%0,%1,%2,%3}, {%4,%5,%6,%7}, {%8,%9}, {%0,%1,%2,%3};"
        : "+f"(c[0]), "+f"(c[1]), "+f"(c[2]), "+f"(c[3])
        : "r"(a0), "r"(a1), "r"(a2), "r"(a3), "r"(b0), "r"(b1));
}

// ---------------- weight pre-split kernels (run once) ----------------------
__global__ void prep_split_ih(const float* __restrict__ W_ih) {
    int i = blockIdx.x * 256 + threadIdx.x;
    if (i >= GATE_N * ENCD) return;
    int n = i / ENCD, k = i % ENCD;
    float v = W_ih[(size_t)n * 2560 + 512 + k];
    unsigned int hi = f2tf32(v);
    float hif = __uint_as_float(hi);
    g_wih_hi[i] = hif;
    g_wih_lo[i] = __uint_as_float(f2tf32(v - hif));
}

__global__ void prep_split_hh(const float* __restrict__ W_hh,
                              const float* __restrict__ W_dec) {
    int i = blockIdx.x * 256 + threadIdx.x;
    if (i >= 2048 * DECD) return;
    int n = i / DECD, k = i % DECD;
    float v = (n < GATE_N) ? W_hh[(size_t)n * DECD + k]
                           : W_dec[(size_t)(n - GATE_N) * DECD + k];
    unsigned int hi = f2tf32(v);
    float hif = __uint_as_float(hi);
    g_whh_hi[i] = hif;
    g_whh_lo[i] = __uint_as_float(f2tf32(v - hif));
}

// ---------------- tf32 GEMM: C = A * B^T + bias, tile 128x64, pipelined ----
// (R8-measured: 42us on att1 -> keep unchanged)
template <int REMAP>
__global__ __launch_bounds__(256) void gemm_tf32(
    const float* __restrict__ A, int lda,
    const float* __restrict__ Bm, int ldb,
    const float* __restrict__ bias, float* __restrict__ C,
    int M, int N, int K)
{
    __shared__ unsigned int sA[128][36];
    __shared__ unsigned int sB[64][36];
    const int tid = threadIdx.x;
    const int warp = tid >> 5, lane = tid & 31;
    const int m0 = blockIdx.x * 128, n0 = blockIdx.y * 64;
    const int wm = (warp >> 1) * 32;
    const int wn = (warp & 1) * 32;
    const int gid = lane >> 2;
    const int tig = lane & 3;

    float acc[2][4][4];
#pragma unroll
    for (int mt = 0; mt < 2; mt++)
#pragma unroll
        for (int nt = 0; nt < 4; nt++)
#pragma unroll
            for (int r = 0; r < 4; r++) acc[mt][nt][r] = 0.f;

    const float4 z4 = make_float4(0.f, 0.f, 0.f, 0.f);
    float4 fA[4], fB[2];

#pragma unroll
    for (int it = 0; it < 4; it++) {
        int v = tid + it * 256, row = v >> 3, c4 = v & 7, gm = m0 + row;
        fA[it] = (gm < M) ? *(const float4*)&A[(size_t)gm * lda + c4 * 4] : z4;
    }
#pragma unroll
    for (int it = 0; it < 2; it++) {
        int v = tid + it * 256, row = v >> 3, c4 = v & 7, gn = n0 + row;
        fB[it] = (gn < N) ? *(const float4*)&Bm[(size_t)gn * ldb + c4 * 4] : z4;
    }

    for (int kc = 0; kc < K; kc += 32) {
#pragma unroll
        for (int it = 0; it < 4; it++) {
            int v = tid + it * 256, row = v >> 3, c4 = v & 7;
            unsigned int* d = &sA[row][c4 * 4];
            d[0] = f2tf32(fA[it].x); d[1] = f2tf32(fA[it].y);
            d[2] = f2tf32(fA[it].z); d[3] = f2tf32(fA[it].w);
        }
#pragma unroll
        for (int it = 0; it < 2; it++) {
            int v = tid + it * 256, row = v >> 3, c4 = v & 7;
            unsigned int* d = &sB[row][c4 * 4];
            d[0] = f2tf32(fB[it].x); d[1] = f2tf32(fB[it].y);
            d[2] = f2tf32(fB[it].z); d[3] = f2tf32(fB[it].w);
        }
        __syncthreads();

        if (kc + 32 < K) {
            const int kn = kc + 32;
#pragma unroll
            for (int it = 0; it < 4; it++) {
                int v = tid + it * 256, row = v >> 3, c4 = v & 7, gm = m0 + row;
                fA[it] = (gm < M) ? *(const float4*)&A[(size_t)gm * lda + kn + c4 * 4] : z4;
            }
#pragma unroll
            for (int it = 0; it < 2; it++) {
                int v = tid + it * 256, row = v >> 3, c4 = v & 7, gn = n0 + row;
                fB[it] = (gn < N) ? *(const float4*)&Bm[(size_t)gn * ldb + kn + c4 * 4] : z4;
            }
        }

#pragma unroll
        for (int k8 = 0; k8 < 4; k8++) {
            const int kb = k8 * 8;
            unsigned int b0[4], b1[4];
#pragma unroll
            for (int nt = 0; nt < 4; nt++) {
                int rB = wn + nt * 8 + gid;
                b0[nt] = sB[rB][kb + tig];
                b1[nt] = sB[rB][kb + tig + 4];
            }
#pragma unroll
            for (int mt = 0; mt < 2; mt++) {
                int rA = wm + mt * 16 + gid;
                unsigned int a0 = sA[rA][kb + tig];
                unsigned int a1 = sA[rA + 8][kb + tig];
                unsigned int a2 = sA[rA][kb + tig + 4];
                unsigned int a3 = sA[rA + 8][kb + tig + 4];
#pragma unroll
                for (int nt = 0; nt < 4; nt++)
                    mma_tf32(acc[mt][nt], a0, a1, a2, a3, b0[nt], b1[nt]);
            }
        }
        __syncthreads();
    }

#pragma unroll
    for (int mt = 0; mt < 2; mt++) {
#pragma unroll
        for (int half = 0; half < 2; half++) {
            int gm = m0 + wm + mt * 16 + gid + half * 8;
            if (gm >= M) continue;
            size_t base;
            if (REMAP) {
                int t = gm >> 6, bb = gm & 63;
                base = ((size_t)bb * NSTEP + t) * VOC;
            } else {
                base = (size_t)gm * N;
            }
#pragma unroll
            for (int nt = 0; nt < 4; nt++) {
                int gn = n0 + wn + nt * 8 + tig * 2;
                if (gn < N)     C[base + gn]     = acc[mt][nt][half * 2 + 0] + bias[gn];
                if (gn + 1 < N) C[base + gn + 1] = acc[mt][nt][half * 2 + 1] + bias[gn + 1];
            }
        }
    }
}

// ---------------- per-step gate GEMM, 3xTF32, pre-split weights ------------
// phase 0: [gh | att2] = h @ [W_hh; W_dec]^T   (M=64, N=2048, K=512, grid (16,4))
// phase 1: gi_ctx      = ctx @ W_ih_ctx^T      (M=64, N=1536, K=2048, grid (12,8))
// Tile 64x128; 256 threads = 8 warps (2m x 4n). atomicAdd into zeroed buffers.
__global__ __launch_bounds__(256) void gate_gemm(
    int phase, const float* __restrict__ xh_base)
{
    const float* A;
    const float* Whi;
    const float* Wlo;
    int ldb, Kchunk;
    if (phase == 0) { A = xh_base + 2560; Whi = g_whh_hi; Wlo = g_whh_lo; ldb = 512;  Kchunk = 128; }
    else            { A = xh_base + 512;  Whi = g_wih_hi; Wlo = g_wih_lo; ldb = 2048; Kchunk = 256; }
    const int n0 = blockIdx.x * 128;
    const int k0 = blockIdx.y * Kchunk;

    __shared__ unsigned int sAhi[64][36], sAlo[64][36];
    __shared__ unsigned int sBhi[128][36], sBlo[128][36];
    const int tid = threadIdx.x;
    const int warp = tid >> 5, lane = tid & 31;
    const int wm = (warp & 1) * 32;
    const int wn = (warp >> 1) * 32;
    const int gid = lane >> 2;
    const int tig = lane & 3;

    float acc[2][4][4];
#pragma unroll
    for (int mt = 0; mt < 2; mt++)
#pragma unroll
        for (int nt = 0; nt < 4; nt++)
#pragma unroll
            for (int r = 0; r < 4; r++) acc[mt][nt][r] = 0.f;

    for (int kc = 0; kc < Kchunk; kc += 32) {
        // A fill: 64x32, on-the-fly hi/lo split (only 8 floats/thread)
#pragma unroll
        for (int it = 0; it < 2; it++) {
            int v = tid + it * 256, row = v >> 3, c4 = v & 7;
            float4 f = *(const float4*)&A[(size_t)row * XH_W + k0 + kc + c4 * 4];
            float fv[4] = {f.x, f.y, f.z, f.w};
            unsigned int* dh = &sAhi[row][c4 * 4];
            unsigned int* dl = &sAlo[row][c4 * 4];
#pragma unroll
            for (int j = 0; j < 4; j++) {
                unsigned int hi = f2tf32(fv[j]);
                dh[j] = hi;
                dl[j] = f2tf32(fv[j] - __uint_as_float(hi));
            }
        }
        // B fill: 128x32 from pre-split weights, pure loads
#pragma unroll
        for (int it = 0; it < 4; it++) {
            int v = tid + it * 256, row = v >> 3, c4 = v & 7;
            size_t off = (size_t)(n0 + row) * ldb + k0 + kc + c4 * 4;
            float4 h4 = *(const float4*)&Whi[off];
            float4 l4 = *(const float4*)&Wlo[off];
            unsigned int* dh = &sBhi[row][c4 * 4];
            unsigned int* dl = &sBlo[row][c4 * 4];
            dh[0] = __float_as_uint(h4.x); dh[1] = __float_as_uint(h4.y);
            dh[2] = __float_as_uint(h4.z); dh[3] = __float_as_uint(h4.w);
            dl[0] = __float_as_uint(l4.x); dl[1] = __float_as_uint(l4.y);
            dl[2] = __float_as_uint(l4.z); dl[3] = __float_as_uint(l4.w);
        }
        __syncthreads();

#pragma unroll
        for (int k8 = 0; k8 < 4; k8++) {
            const int kb = k8 * 8;
            unsigned int bh0[4], bh1[4], bl0[4], bl1[4];
#pragma unroll
            for (int nt = 0; nt < 4; nt++) {
                int rB = wn + nt * 8 + gid;
                bh0[nt] = sBhi[rB][kb + tig];
                bh1[nt] = sBhi[rB][kb + tig + 4];
                bl0[nt] = sBlo[rB][kb + tig];
                bl1[nt] = sBlo[rB][kb + tig + 4];
            }
#pragma unroll
            for (int mt = 0; mt < 2; mt++) {
                int rA = wm + mt * 16 + gid;
                unsigned int ah0 = sAhi[rA][kb + tig];
                unsigned int ah1 = sAhi[rA + 8][kb + tig];
                unsigned int ah2 = sAhi[rA][kb + tig + 4];
                unsigned int ah3 = sAhi[rA + 8][kb + tig + 4];
                unsigned int al0 = sAlo[rA][kb + tig];
                unsigned int al1 = sAlo[rA + 8][kb + tig];
                unsigned int al2 = sAlo[rA][kb + tig + 4];
                unsigned int al3 = sAlo[rA + 8][kb + tig + 4];
#pragma unroll
                for (int nt = 0; nt < 4; nt++) {
                    mma_tf32(acc[mt][nt], ah0, ah1, ah2, ah3, bl0[nt], bl1[nt]);
                    mma_tf32(acc[mt][nt], al0, al1, al2, al3, bh0[nt], bh1[nt]);
                    mma_tf32(acc[mt][nt], ah0, ah1, ah2, ah3, bh0[nt], bh1[nt]);
                }
            }
        }
        __syncthreads();
    }

    float* gh = g_gates + (size_t)BATCH * GATE_N;
#pragma unroll
    for (int mt = 0; mt < 2; mt++)
#pragma unroll
        for (int half = 0; half < 2; half++) {
            int gm = wm + mt * 16 + gid + half * 8;      // 0..63
#pragma unroll
            for (int nt = 0; nt < 4; nt++) {
                int gn = n0 + wn + nt * 8 + tig * 2;
                float v0 = acc[mt][nt][half * 2 + 0];
                float v1 = acc[mt][nt][half * 2 + 1];
                if (phase == 1) {
                    atomicAdd(&g_gates[(size_t)gm * GATE_N + gn],     v0);
                    atomicAdd(&g_gates[(size_t)gm * GATE_N + gn + 1], v1);
                } else if (gn < GATE_N) {
                    atomicAdd(&gh[(size_t)gm * GATE_N + gn],     v0);
                    atomicAdd(&gh[(size_t)gm * GATE_N + gn + 1], v1);
                } else {
                    atomicAdd(&g_att2[gm * ATTD + gn - GATE_N],     v0);
                    atomicAdd(&g_att2[gm * ATTD + gn - GATE_N + 1], v1);
                }
            }
        }
}

// ---------------- attention scores + softmax (block per batch) -------------
__global__ __launch_bounds__(256) void attn_scores(
    const float* __restrict__ b_dec,
    const float* __restrict__ w_full, const float* __restrict__ b_full)
{
    const int b = blockIdx.x;
    const int tid = threadIdx.x;
    const int lane = tid & 31, warp = tid >> 5;
    __shared__ __align__(16) float satt2[ATTD];
    __shared__ __align__(16) float se[PIX];
    __shared__ float sred[16];

    // att2 (computed by gate_gemm phase 0) + b_dec; then clear for next step
    for (int a = tid; a < ATTD; a += 256) {
        satt2[a] = g_att2[b * ATTD + a] + b_dec[a];
        g_att2[b * ATTD + a] = 0.f;
    }
    __syncthreads();

    const float* att1b = g_att1 + (size_t)b * PIX * ATTD;
    const float4* satt2v = (const float4*)satt2;
    const float4* wfv = (const float4*)w_full;
    for (int p = warp; p < PIX; p += 8) {
        const float4* ar = (const float4*)(att1b + (size_t)p * ATTD);
        float s = 0.f;
#pragma unroll
        for (int a = lane; a < 128; a += 32) {
            float4 x = ar[a]; float4 t2 = satt2v[a]; float4 w = wfv[a];
            s += tanh_fast(x.x + t2.x) * w.x + tanh_fast(x.y + t2.y) * w.y
               + tanh_fast(x.z + t2.z) * w.z + tanh_fast(x.w + t2.w) * w.w;
        }
#pragma unroll
        for (int o = 16; o; o >>= 1) s += __shfl_xor_sync(0xffffffffu, s, o);
        if (lane == 0) se[p] = s + b_full[0];
    }
    __syncthreads();

    // softmax over 196
    float lm = -3.4e38f;
    for (int p = tid; p < PIX; p += 256) lm = fmaxf(lm, se[p]);
#pragma unroll
    for (int o = 16; o; o >>= 1) lm = fmaxf(lm, __shfl_xor_sync(0xffffffffu, lm, o));
    if (lane == 0) sred[warp] = lm;
    __syncthreads();
    if (warp == 0) {
        float v = (lane < 8) ? sred[lane] : -3.4e38f;
#pragma unroll
        for (int o = 16; o; o >>= 1) v = fmaxf(v, __shfl_xor_sync(0xffffffffu, v, o));
        if (lane == 0) sred[8] = v;
    }
    __syncthreads();
    const float gmax = sred[8];
    float ls = 0.f;
    for (int p = tid; p < PIX; p += 256) {
        float ex = expf(se[p] - gmax);
        se[p] = ex;
        ls += ex;
    }
#pragma unroll
    for (int o = 16; o; o >>= 1) ls += __shfl_xor_sync(0xffffffffu, ls, o);
    if (lane == 0) sred[warp] = ls;
    __syncthreads();
    if (warp == 0) {
        float v = (lane < 8) ? sred[lane] : 0.f;
#pragma unroll
        for (int o = 16; o; o >>= 1) v += __shfl_xor_sync(0xffffffffu, v, o);
        if (lane == 0) sred[9] = v;
    }
    __syncthreads();
    const float sinv = 1.f / sred[9];
    for (int p = tid; p < PIX; p += 256)
        g_alpha[b * PIX + p] = se[p] * sinv;
}

// ---------------- context gather: grid (64, 8) -----------------------------
// y&1 = column half (256 float4), y>>1 = p-quarter (49 pixels). atomicAdd
// partial contexts into xh ctx region (zeroed by gru_gates of prior step).
__global__ __launch_bounds__(256) void attn_context(const float* __restrict__ enc)
{
    const int b = blockIdx.x;
    const int colhalf = blockIdx.y & 1;
    const int q = blockIdx.y >> 1;
    const int tid = threadIdx.x;
    __shared__ float sa[49];
    if (tid < 49) sa[tid] = g_alpha[b * PIX + q * 49 + tid];
    __syncthreads();

    const int col4 = colhalf * 256 + tid;
    const float4* encb = (const float4*)(enc + (size_t)b * PIX * ENCD)
                         + (size_t)(q * 49) * 512 + col4;
    float4 c = make_float4(0.f, 0.f, 0.f, 0.f);
#pragma unroll 7
    for (int j = 0; j < 49; j++) {
        float4 v = encb[(size_t)j * 512];
        float a = sa[j];
        c.x += a * v.x; c.y += a * v.y; c.z += a * v.z; c.w += a * v.w;
    }
    float* dst = g_xh + (size_t)b * XH_W + 512 + col4 * 4;
    atomicAdd(dst + 0, c.x); atomicAdd(dst + 1, c.y);
    atomicAdd(dst + 2, c.z); atomicAdd(dst + 3, c.w);
}

// ---------------- GRU gate activations + h update + read-and-clear ---------
__global__ __launch_bounds__(256) void gru_gates(
    int t, const float* __restrict__ b_hh)
{
    int idx = blockIdx.x * 256 + threadIdx.x;
    if (idx >= BATCH * DECD) return;
    int b = idx >> 9, d = idx & 511;
    float* gi = g_gates + (size_t)b * GATE_N;
    float* gh = g_gates + (size_t)BATCH * GATE_N + (size_t)b * GATE_N;
    const float* ge = g_giemb + ((size_t)t * BATCH + b) * GATE_N;  // incl b_ih
    float rr = (gi[d] + ge[d]) + (gh[d] + b_hh[d]);
    float zz = (gi[512 + d] + ge[512 + d]) + (gh[512 + d] + b_hh[512 + d]);
    float inp = gi[1024 + d] + ge[1024 + d];
    float hnp = gh[1024 + d] + b_hh[1024 + d];
    // clear accumulators for next step's atomic GEMMs
    gi[d] = 0.f; gi[512 + d] = 0.f; gi[1024 + d] = 0.f;
    gh[d] = 0.f; gh[512 + d] = 0.f; gh[1024 + d] = 0.f;
    float* xh = g_xh + (size_t)b * XH_W;
    ((float4*)(xh + 512))[d] = make_float4(0.f, 0.f, 0.f, 0.f);  // clear ctx
    float r = 1.f / (1.f + expf(-rr));
    float z = 1.f / (1.f + expf(-zz));
    float n = tanhf(inp + r * hnp);
    float hold = xh[2560 + d];
    float hnew = (1.f - z) * n + z * hold;
    xh[2560 + d] = hnew;
    g_hall[((size_t)t * BATCH + b) * DECD + d] = hnew;
}

// ---------------- embedding gather for all steps ---------------------------
__global__ __launch_bounds__(128) void gather_embs(
    const int* __restrict__ captions, const float* __restrict__ emb_table)
{
    int r = blockIdx.x;          // t*64+b
    int t = r >> 6, b = r & 63;
    int tok = captions[b * TT + t];
    const float4* src = (const float4*)(emb_table + (size_t)tok * EMBD);
    ((float4*)(g_emball + (size_t)r * EMBD))[threadIdx.x] = src[threadIdx.x];
}

__global__ void write_caplens(const int* __restrict__ caplens, float* __restrict__ out, int n)
{
    int i = threadIdx.x;
    if (i < n && i < BATCH) out[i] = (float)(caplens[i] - 1);
}

// ---------------- host ----------------
extern "C" void kernel_launch(void* const* d_in, const int* in_sizes, int n_in,
                              void* d_out, int out_size)
{
    const float* enc       = (const float*)d_in[0];
    const int*   captions  = (const int*)  d_in[1];
    const int*   caplens   = (const int*)  d_in[2];
    const float* emb_table = (const float*)d_in[3];
    const float* W_enc     = (const float*)d_in[4];
    const float* b_enc     = (const float*)d_in[5];
    const float* W_dec     = (const float*)d_in[6];
    const float* b_dec     = (const float*)d_in[7];
    const float* w_full    = (const float*)d_in[8];
    const float* b_full    = (const float*)d_in[9];
    const float* W_ih      = (const float*)d_in[10];
    const float* b_ih      = (const float*)d_in[11];
    const float* W_hh      = (const float*)d_in[12];
    const float* b_hh      = (const float*)d_in[13];
    const float* W_fc      = (const float*)d_in[14];
    const float* b_fc      = (const float*)d_in[15];
    float* out = (float*)d_out;

    float *att1p, *xhp, *hallp, *emballp, *giembp, *gatesp, *att2p;
    cudaGetSymbolAddress((void**)&att1p, g_att1);
    cudaGetSymbolAddress((void**)&xhp, g_xh);
    cudaGetSymbolAddress((void**)&hallp, g_hall);
    cudaGetSymbolAddress((void**)&emballp, g_emball);
    cudaGetSymbolAddress((void**)&giembp, g_giemb);
    cudaGetSymbolAddress((void**)&gatesp, g_gates);
    cudaGetSymbolAddress((void**)&att2p, g_att2);

    // initial zeros: h0 + ctx (xh), gate accumulators, att2
    zerok<<<(BATCH * XH_W + 255) / 256, 256>>>(xhp, BATCH * XH_W);
    zerok<<<(2 * BATCH * GATE_N + 255) / 256, 256>>>(gatesp, 2 * BATCH * GATE_N);
    zerok<<<(BATCH * ATTD + 255) / 256, 256>>>(att2p, BATCH * ATTD);

    // one-time prep
    gather_embs<<<MROWS, 128>>>(captions, emb_table);
    prep_split_ih<<<(GATE_N * ENCD + 255) / 256, 256>>>(W_ih);
    prep_split_hh<<<(2048 * DECD + 255) / 256, 256>>>(W_hh, W_dec);

    // att1 = enc @ W_enc^T + b_enc : [12544,2048]x[2048,512]
    gemm_tf32<0><<<dim3(98, 8), 256>>>(enc, ENCD, W_enc, ENCD, b_enc, att1p,
                                       BATCH * PIX, ATTD, ENCD);

    // gi_emb = embs @ W_ih[:, :512]^T + b_ih : [1984,512]x[512,1536]
    gemm_tf32<0><<<dim3(16, 24), 256>>>(emballp, EMBD, W_ih, EMBD + ENCD,
                                        b_ih, giembp, MROWS, GATE_N, EMBD);

    for (int t = 0; t < NSTEP; t++) {
        gate_gemm<<<dim3(16, 4), 256>>>(0, xhp);           // gh + att2 (uses h_{t-1})
        attn_scores<<<BATCH, 256>>>(b_dec, w_full, b_full);
        attn_context<<<dim3(BATCH, 8), 256>>>(enc);
        gate_gemm<<<dim3(12, 8), 256>>>(1, xhp);           // gi_ctx (uses context)
        gru_gates<<<(BATCH * DECD + 255) / 256, 256>>>(t, b_hh);
    }

    // logits = h_all @ W_fc^T + b_fc, stored as [b, t, v]
    gemm_tf32<1><<<dim3(16, 469), 256>>>(hallp, DECD, W_fc, DECD, b_fc, out,
                                         MROWS, VOC, DECD);

    long long NLOG = (long long)BATCH * NSTEP * VOC;
    if ((long long)out_size > NLOG) {
        int rem = (int)((long long)out_size - NLOG);
        write_caplens<<<1, 64>>>(caplens, out + NLOG, rem);
    }
}